// round 11
// baseline (speedup 1.0000x reference)
#include <cuda_runtime.h>
#include <math_constants.h>
#include <stdint.h>

#define NB     128        // batch rows = blocks
#define NV     128256     // vocab
#define NV4    (NV / 4)   // 32064 float4s per row
#define NTHR   1024
#define NWARP  (NTHR / 32)

// Accurate -log(x) for x > 0. Relative error ~1e-7 incl. x near 1
// (f = m-1 exact by Sterbenz; no ln2 cancellation).
__device__ __forceinline__ float neg_log_acc(float x) {
    int ix = __float_as_int(x);
    int k  = (ix - 0x3f3504f3) & 0xff800000;   // reduce mantissa to [sqrt(.5), sqrt(2))
    float m = __int_as_float(ix - k);
    float e = (float)(k >> 23);
    float f = m - 1.0f;
    float s = __fdividef(f, 2.0f + f);          // |s| <= 0.1716
    float s2 = s * s;
    float p = fmaf(s2, fmaf(s2, fmaf(s2, 0.14285715f, 0.2f), 0.33333334f), 1.0f);
    float lm = (2.0f * s) * p;                  // log(m) = 2*atanh(s)
    return -fmaf(e, 0.69314718f, lm);
}

__device__ __forceinline__ float sample_key(float l, float uv, float invT) {
    l = (l == l) ? l : 0.0f;                               // nan_to_num
    float uc = fminf(fmaxf(uv, 1e-10f), 0.99999988f);      // clip to f32(1 - 1e-7)
    float w  = neg_log_acc(uc);                            // -log(u) in (1.19e-7, 23.03): finite > 0
    float g  = -__logf(w);                                 // outer log: approx ok, finite
    return fmaf(l, invT, g);                               // l/T + gumbel: always finite
}

__global__ __launch_bounds__(NTHR)
void sampler_kernel(const float* __restrict__ bigA,
                    const float* __restrict__ temps,
                    const float* __restrict__ bigB,
                    float* __restrict__ out) {
    // ---- device-side role disambiguation: which big array is `logits`? ----
    // u ~ Uniform(0,1) lies in [0,1]; logits ~ Normal(0,1): P(32 consecutive
    // values all in [0,1]) ~ 1e-15. Probe is deterministic & block-uniform.
    const int lid32 = threadIdx.x & 31;
    float pa = bigA[lid32];
    float pb = bigB[lid32];
    bool a_out = !(pa >= 0.0f && pa <= 1.0f);   // true also on NaN
    bool b_out = !(pb >= 0.0f && pb <= 1.0f);
    unsigned va = __ballot_sync(0xFFFFFFFFu, a_out);
    unsigned vb = __ballot_sync(0xFFFFFFFFu, b_out);
    bool a_is_logits = (va != 0u) || (vb == 0u); // ambiguous -> metadata order
    const float* logits = a_is_logits ? bigA : bigB;
    const float* u      = a_is_logits ? bigB : bigA;

    const int row  = blockIdx.x;
    const long base = (long)row * NV;
    const float4* __restrict__ lg = (const float4*)(logits + base);
    const float4* __restrict__ uu = (const float4*)(u + base);

    // ---- temperature (sanitized: garbage can never NaN the keys) ----
    float T = temps[row];
    if (!(T == T)) T = 1.0f;                    // NaN guard
    const bool greedy = (T <= 1e-6f);
    float invT = 1.0f / fmaxf(T, 1e-6f);
    if (!(invT == invT) || invT > 1e7f) invT = 1e6f;

    float bk = -CUDART_INF_F;
    int   bi = 0;

    if (greedy) {
        // key = nan_to_num(logit); u untouched
        for (int i = threadIdx.x; i < NV4; i += NTHR) {
            float4 l4 = lg[i];
            int gi = i * 4;
            float v;
            v = l4.x; v = (v == v) ? v : 0.0f; if (v > bk) { bk = v; bi = gi;     }
            v = l4.y; v = (v == v) ? v : 0.0f; if (v > bk) { bk = v; bi = gi + 1; }
            v = l4.z; v = (v == v) ? v : 0.0f; if (v > bk) { bk = v; bi = gi + 2; }
            v = l4.w; v = (v == v) ? v : 0.0f; if (v > bk) { bk = v; bi = gi + 3; }
        }
    } else {
        for (int i = threadIdx.x; i < NV4; i += NTHR) {
            float4 l4 = lg[i];
            float4 u4 = uu[i];
            int gi = i * 4;
            float k;
            k = sample_key(l4.x, u4.x, invT); if (k > bk) { bk = k; bi = gi;     }
            k = sample_key(l4.y, u4.y, invT); if (k > bk) { bk = k; bi = gi + 1; }
            k = sample_key(l4.z, u4.z, invT); if (k > bk) { bk = k; bi = gi + 2; }
            k = sample_key(l4.w, u4.w, invT); if (k > bk) { bk = k; bi = gi + 3; }
        }
    }
    // Ascending per-thread visit order + strict '>' -> first occurrence wins.

    // ---- block argmax reduction, lowest-index tie-break ----
    const unsigned full = 0xFFFFFFFFu;
    #pragma unroll
    for (int off = 16; off > 0; off >>= 1) {
        float ok = __shfl_down_sync(full, bk, off);
        int   oi = __shfl_down_sync(full, bi, off);
        if (ok > bk || (ok == bk && oi < bi)) { bk = ok; bi = oi; }
    }

    __shared__ float skey[NWARP];
    __shared__ int   sidx[NWARP];
    const int wid = threadIdx.x >> 5;
    const int lid = threadIdx.x & 31;
    if (lid == 0) { skey[wid] = bk; sidx[wid] = bi; }
    __syncthreads();

    if (wid == 0) {
        bk = (lid < NWARP) ? skey[lid] : -CUDART_INF_F;
        bi = (lid < NWARP) ? sidx[lid] : 0x7FFFFFFF;
        #pragma unroll
        for (int off = 16; off > 0; off >>= 1) {
            float ok = __shfl_down_sync(full, bk, off);
            int   oi = __shfl_down_sync(full, bi, off);
            if (ok > bk || (ok == bk && oi < bi)) { bk = ok; bi = oi; }
        }
        // OUTPUT CONTRACT: harness reads d_out as float32 -> store the index
        // as a float VALUE (indices < 2^24: exactly representable).
        if (lid == 0) out[row] = (float)bi;
    }
}

extern "C" void kernel_launch(void* const* d_in, const int* in_sizes, int n_in,
                              void* d_out, int out_size) {
    // Identify the unique size-128 input as temperatures; pass the two big
    // arrays through in metadata order — kernel resolves their roles by value.
    const float* temps  = nullptr;
    const float* big[2] = {nullptr, nullptr};
    int nbig = 0;
    for (int i = 0; i < n_in && i < 8; i++) {
        const float* p = (const float*)d_in[i];
        if (in_sizes[i] == NB && temps == nullptr) temps = p;
        else if (nbig < 2)                         big[nbig++] = p;
    }
    if (!temps || nbig < 2) {           // fallback: positional
        big[0] = (const float*)d_in[0];
        temps  = (const float*)d_in[1];
        big[1] = (const float*)d_in[2];
    }
    float* out = (float*)d_out;

    sampler_kernel<<<NB, NTHR>>>(big[0], temps, big[1], out);
}